// round 13
// baseline (speedup 1.0000x reference)
#include <cuda_runtime.h>
#include <cuda_bf16.h>
#include <math.h>
#include <stdint.h>

#define T    2048
#define D    512
#define NH   8
#define DH   64
#define NI   4
#define DI   64
#define KSEL 128
#define NB   2560   // packed wide-GEMM N: Wq|Wk|Wv|Wvg|Wog = 5*512
#define NQKV 1536   // 3-term (split) portion
#define NIW  384    // packed index GEMM N: qi(256)|ki(64)|w(4)|pad

// offsets inside packed projection row
#define OQ   0
#define OK_  512
#define OV   1024
#define OVG  1536
#define OOG  2048
// offsets inside packed index row
#define OIQ  0
#define OIK  256
#define OIW  320

// ---------------- scratch (device globals; no allocation allowed) ----------------
__device__ __align__(256) float g_big[(size_t)T*NB];
__device__ __align__(256) float g_k [T*D];
__device__ __align__(256) float g_v [T*D];
__device__ __align__(256) float g_ix[(size_t)T*NIW];
__device__ __align__(256) float g_Wi[(size_t)D*NIW];
__device__ __align__(256) float g_sc[(size_t)T*T];
__device__ __align__(256) float g_cs[T*32];
__device__ __align__(256) float g_sn[T*32];

__device__ __align__(256) __nv_bfloat16 g_Ah[T*D],  g_Al[T*D];
__device__ __align__(256) __nv_bfloat16 g_Bh[(size_t)D*NB], g_Bl[(size_t)D*NB];
__device__ __align__(256) __nv_bfloat16 g_AoH[T*D], g_AoL[T*D];
__device__ __align__(256) __nv_bfloat16 g_WoH[D*D], g_WoL[D*D];

// ---------------- tensor-core helpers ----------------
__device__ __forceinline__ void cpa16(void* dst, const void* src) {
    uint32_t d = (uint32_t)__cvta_generic_to_shared(dst);
    asm volatile("cp.async.cg.shared.global [%0],[%1],16;\n" :: "r"(d), "l"(src));
}
__device__ __forceinline__ void cp_commit() { asm volatile("cp.async.commit_group;\n"); }

__device__ __forceinline__ void ldsm_x4(uint32_t* r, const void* p) {
    uint32_t a = (uint32_t)__cvta_generic_to_shared(p);
    asm volatile("ldmatrix.sync.aligned.m8n8.x4.shared.b16 {%0,%1,%2,%3},[%4];"
                 : "=r"(r[0]), "=r"(r[1]), "=r"(r[2]), "=r"(r[3]) : "r"(a));
}
__device__ __forceinline__ void ldsm_x2t(uint32_t* r, const void* p) {
    uint32_t a = (uint32_t)__cvta_generic_to_shared(p);
    asm volatile("ldmatrix.sync.aligned.m8n8.x2.trans.shared.b16 {%0,%1},[%2];"
                 : "=r"(r[0]), "=r"(r[1]) : "r"(a));
}
__device__ __forceinline__ void mma16816(float* c, const uint32_t* a, const uint32_t* b) {
    asm volatile("mma.sync.aligned.m16n8k16.row.col.f32.bf16.bf16.f32 "
                 "{%0,%1,%2,%3},{%4,%5,%6,%7},{%8,%9},{%0,%1,%2,%3};"
                 : "+f"(c[0]), "+f"(c[1]), "+f"(c[2]), "+f"(c[3])
                 : "r"(a[0]), "r"(a[1]), "r"(a[2]), "r"(a[3]), "r"(b[0]), "r"(b[1]));
}

// ---------------- split fp32 -> (bf16 hi, bf16 lo) ----------------
__global__ __launch_bounds__(256) void split_kernel(
    const float* __restrict__ src, __nv_bfloat16* __restrict__ h,
    __nv_bfloat16* __restrict__ l, int n)
{
    int i = blockIdx.x * 256 + threadIdx.x;
    if (i < n) {
        float f = src[i];
        __nv_bfloat16 hh = __float2bfloat16_rn(f);
        float r = f - __bfloat162float(hh);
        h[i] = hh;
        l[i] = __float2bfloat16_rn(r);
    }
}

// ---------------- pack 5 weight matrices into B[512][NB] (split bf16) ----------------
__global__ __launch_bounds__(256) void packB_kernel(
    const float* __restrict__ Wq, const float* __restrict__ Wk,
    const float* __restrict__ Wv, const float* __restrict__ Wvg,
    const float* __restrict__ Wog)
{
    int i = blockIdx.x * 256 + threadIdx.x;
    if (i >= D * NB) return;
    int k = i / NB, c = i % NB;
    float f;
    if      (c < 1024) f = (c < 512)  ? Wq [k*512 + c]        : Wk [k*512 + c - 512];
    else if (c < 2048) f = (c < 1536) ? Wv [k*512 + c - 1024] : Wvg[k*512 + c - 1536];
    else               f = Wog[k*512 + c - 2048];
    __nv_bfloat16 hh = __float2bfloat16_rn(f);
    g_Bh[i] = hh;
    g_Bl[i] = __float2bfloat16_rn(f - __bfloat162float(hh));
}

// ---------------- pack index weights (fp32, exact) ----------------
__global__ __launch_bounds__(256) void packWi_kernel(
    const float* __restrict__ Wiq, const float* __restrict__ Wik,
    const float* __restrict__ Wiw)
{
    int i = blockIdx.x * 256 + threadIdx.x;
    if (i >= D * NIW) return;
    int k = i / NIW, c = i % NIW;
    float f;
    if      (c < 256) f = Wiq[k*256 + c];
    else if (c < 320) f = Wik[k*64  + c - 256];
    else if (c < 324) f = Wiw[k*4   + c - 320];
    else              f = 0.f;
    g_Wi[i] = f;
}

// ---------------- split-bf16 tensor-core GEMM (TERMS=3 split / TERMS=1 plain bf16) ----------------
#define SA_STRIDE 40
#define SB_STRIDE 136
#define SA_SZ (128*SA_STRIDE)
#define SB_SZ (32*SB_STRIDE)
#define GEMM_SMEM ((2*2*SA_SZ + 2*2*SB_SZ)*2)

template<int TERMS>
__global__ __launch_bounds__(256) void mma_gemm(
    const __nv_bfloat16* __restrict__ Ah, const __nv_bfloat16* __restrict__ Al,
    const __nv_bfloat16* __restrict__ Bh, const __nv_bfloat16* __restrict__ Bl,
    float* __restrict__ C, int M, int N, int K, int Nw)
{
    extern __shared__ __align__(16) char smem_raw[];
    __nv_bfloat16* sA = (__nv_bfloat16*)smem_raw;
    __nv_bfloat16* sB = (__nv_bfloat16*)(smem_raw + 2*2*SA_SZ*2);
    const int tid = threadIdx.x;
    const int m0 = blockIdx.y * 128, n0 = blockIdx.x * 128;
    (void)Nw;

    const int wid = tid >> 5, lane = tid & 31;
    const int m0w = (wid & 1) * 64, n0w = (wid >> 1) * 32;
    const int a_row = (lane & 15);
    const int a_koff = (lane >> 4) * 8;
    const int l15 = lane & 15;
    const int b_krow = (l15 & 7) + (l15 >> 3) * 8;

    float acc[4][4][4];
    #pragma unroll
    for (int i = 0; i < 4; ++i)
        #pragma unroll
        for (int j = 0; j < 4; ++j)
            #pragma unroll
            for (int r = 0; r < 4; ++r) acc[i][j][r] = 0.f;

    auto load_stage = [&](int st, int k0) {
        __nv_bfloat16* aH = sA + (st*2+0)*SA_SZ;
        __nv_bfloat16* aL = sA + (st*2+1)*SA_SZ;
        __nv_bfloat16* bH = sB + (st*2+0)*SB_SZ;
        __nv_bfloat16* bL = sB + (st*2+1)*SB_SZ;
        #pragma unroll
        for (int i = 0; i < 2; ++i) {
            int c = tid + i * 256;
            int r = c >> 2, cc = (c & 3) * 8;
            cpa16(aH + r*SA_STRIDE + cc, Ah + (size_t)(m0 + r) * K + k0 + cc);
            if (TERMS == 3)
                cpa16(aL + r*SA_STRIDE + cc, Al + (size_t)(m0 + r) * K + k0 + cc);
            int rb = c >> 4, cb = (c & 15) * 8;
            cpa16(bH + rb*SB_STRIDE + cb, Bh + (size_t)(k0 + rb) * N + n0 + cb);
            if (TERMS == 3)
                cpa16(bL + rb*SB_STRIDE + cb, Bl + (size_t)(k0 + rb) * N + n0 + cb);
        }
        cp_commit();
    };

    load_stage(0, 0);
    const int KT = K / 32;
    for (int kt = 0; kt < KT; ++kt) {
        if (kt + 1 < KT) {
            load_stage((kt + 1) & 1, (kt + 1) * 32);
            asm volatile("cp.async.wait_group 1;\n");
        } else {
            asm volatile("cp.async.wait_group 0;\n");
        }
        __syncthreads();

        const int st = kt & 1;
        const __nv_bfloat16* aP[2] = { sA + (st*2+0)*SA_SZ, sA + (st*2+1)*SA_SZ };
        const __nv_bfloat16* bP[2] = { sB + (st*2+0)*SB_SZ, sB + (st*2+1)*SB_SZ };

        #pragma unroll
        for (int kk = 0; kk < 32; kk += 16) {
            uint32_t af[2][4][4];
            uint32_t bf[2][4][2];
            #pragma unroll
            for (int p = 0; p < (TERMS == 3 ? 2 : 1); ++p) {
                #pragma unroll
                for (int mt = 0; mt < 4; ++mt)
                    ldsm_x4(af[p][mt], aP[p] + (m0w + mt*16 + a_row)*SA_STRIDE + kk + a_koff);
                #pragma unroll
                for (int nt = 0; nt < 4; ++nt)
                    ldsm_x2t(bf[p][nt], bP[p] + (kk + b_krow)*SB_STRIDE + n0w + nt*8);
            }
            #pragma unroll
            for (int mt = 0; mt < 4; ++mt)
                #pragma unroll
                for (int nt = 0; nt < 4; ++nt) {
                    mma16816(acc[mt][nt], af[0][mt], bf[0][nt]);
                    if (TERMS == 3) {
                        mma16816(acc[mt][nt], af[0][mt], bf[1][nt]);
                        mma16816(acc[mt][nt], af[1][mt], bf[0][nt]);
                    }
                }
        }
        __syncthreads();
    }

    #pragma unroll
    for (int mt = 0; mt < 4; ++mt) {
        int row = m0 + m0w + mt*16 + (lane >> 2);
        #pragma unroll
        for (int nt = 0; nt < 4; ++nt) {
            int col = n0 + n0w + nt*8 + (lane & 3)*2;
            *(float2*)(C + (size_t)row * N + col)       = make_float2(acc[mt][nt][0], acc[mt][nt][1]);
            *(float2*)(C + (size_t)(row + 8) * N + col) = make_float2(acc[mt][nt][2], acc[mt][nt][3]);
        }
    }
}

// ---------------- fp32 SIMT SGEMM (exact path for top-k ranking inputs) ----------------
__global__ __launch_bounds__(256) void sgemm_kernel(
    const float* __restrict__ A, const float* __restrict__ B,
    float* __restrict__ C, int M, int N, int K)
{
    __shared__ float Ast[16][68];
    __shared__ float Bs [16][64];
    const int tid = threadIdx.x;
    const int m0 = blockIdx.y * 64, n0 = blockIdx.x * 64;
    const int tr = tid >> 4, tc = tid & 15;
    const int arow = tid >> 2, akq = tid & 3;
    const int brow = tid >> 4, bnq = tid & 15;

    float acc[4][4] = {};

    for (int k0 = 0; k0 < K; k0 += 16) {
        float4 av = *(const float4*)(A + (size_t)(m0 + arow) * K + k0 + akq * 4);
        Ast[akq*4+0][arow] = av.x;
        Ast[akq*4+1][arow] = av.y;
        Ast[akq*4+2][arow] = av.z;
        Ast[akq*4+3][arow] = av.w;

        float4 bv = *(const float4*)(B + (size_t)(k0 + brow) * N + n0 + bnq * 4);
        *(float4*)&Bs[brow][bnq * 4] = bv;
        __syncthreads();

        #pragma unroll
        for (int kk = 0; kk < 16; ++kk) {
            float4 a = *(float4*)&Ast[kk][tr * 4];
            float4 b = *(float4*)&Bs [kk][tc * 4];
            acc[0][0] += a.x * b.x; acc[0][1] += a.x * b.y; acc[0][2] += a.x * b.z; acc[0][3] += a.x * b.w;
            acc[1][0] += a.y * b.x; acc[1][1] += a.y * b.y; acc[1][2] += a.y * b.z; acc[1][3] += a.y * b.w;
            acc[2][0] += a.z * b.x; acc[2][1] += a.z * b.y; acc[2][2] += a.z * b.z; acc[2][3] += a.z * b.w;
            acc[3][0] += a.w * b.x; acc[3][1] += a.w * b.y; acc[3][2] += a.w * b.z; acc[3][3] += a.w * b.w;
        }
        __syncthreads();
    }

    #pragma unroll
    for (int i = 0; i < 4; ++i) {
        int r = m0 + tr * 4 + i;
        #pragma unroll
        for (int j = 0; j < 4; ++j)
            C[(size_t)r * N + n0 + tc * 4 + j] = acc[i][j];
    }
}

// ---------------- RoPE cos/sin table ----------------
__global__ __launch_bounds__(256) void rope_table_kernel()
{
    int i = blockIdx.x * 256 + threadIdx.x;
    if (i >= T * 32) return;
    int t = i >> 5, jm = i & 31;
    float invf = powf(10000.f, -(float)(2 * jm) / 64.f);
    float ph = (float)t * invf;
    float s, c;
    sincosf(ph, &s, &c);
    g_cs[i] = c;
    g_sn[i] = s;
}

// ---------------- RoPE(q,k) + v*sigmoid(vg+bvg) ----------------
__global__ __launch_bounds__(256) void ew_kernel(const float* __restrict__ bvg)
{
    int t = blockIdx.x, tid = threadIdx.x;
    float* row = g_big + (size_t)t * NB;
    __shared__ float sq[D], sk[D];
    sq[tid]       = row[OQ + tid];
    sq[tid + 256] = row[OQ + tid + 256];
    sk[tid]       = row[OK_ + tid];
    sk[tid + 256] = row[OK_ + tid + 256];
    __syncthreads();
    #pragma unroll
    for (int it = 0; it < 2; ++it) {
        int e = tid + it * 256;
        int j = e & 63, jm = j & 31;
        float cc = g_cs[t * 32 + jm], ss = g_sn[t * 32 + jm];
        float rq = (j < 32) ? -sq[e + 32] : sq[e - 32];
        float rk = (j < 32) ? -sk[e + 32] : sk[e - 32];
        row[OQ + e] = sq[e] * cc + rq * ss;
        g_k[(size_t)t * D + e] = sk[e] * cc + rk * ss;
        float vv = row[OV + e], vg = row[OVG + e];
        g_v[(size_t)t * D + e] = vv * (1.f / (1.f + expf(-(vg + bvg[e]))));
    }
}

// ---------------- index scores: 64x64 tile, 4x4/thread, TWO heads per pass ----------------
#define SCW_SMEM (3 * 64 * 68 * 4)

__global__ __launch_bounds__(256) void scores_kernel(const float* __restrict__ idx_bias,
                                                     const float* __restrict__ biw)
{
    const int q0 = blockIdx.y * 64, j0 = blockIdx.x * 64;
    if (j0 > q0 + 63) return;
    extern __shared__ float sdyn[];
    float* Kst = sdyn;
    float* Q0  = sdyn + 64 * 68;
    float* Q1  = sdyn + 2 * 64 * 68;
    const int tid = threadIdx.x;
    const int tr = tid >> 4, tc = tid & 15;

    #pragma unroll
    for (int it = 0; it < 4; ++it) {
        int e = tid + it * 256;
        int r = e >> 4, quad = e & 15;
        float4 kv = *(const float4*)(g_ix + (size_t)(j0 + r) * NIW + OIK + quad * 4);
        Kst[(quad*4+0)*68 + r] = kv.x; Kst[(quad*4+1)*68 + r] = kv.y;
        Kst[(quad*4+2)*68 + r] = kv.z; Kst[(quad*4+3)*68 + r] = kv.w;
    }

    float fin[4][4] = {};
    for (int hp = 0; hp < 2; ++hp) {
        if (hp) __syncthreads();
        const int h0 = 2 * hp, h1 = 2 * hp + 1;
        #pragma unroll
        for (int it = 0; it < 4; ++it) {
            int e = tid + it * 256;
            int r = e >> 4, quad = e & 15;
            const float* base = g_ix + (size_t)(q0 + r) * NIW + OIQ;
            float4 qa = *(const float4*)(base + h0 * DI + quad * 4);
            float4 qb = *(const float4*)(base + h1 * DI + quad * 4);
            Q0[(quad*4+0)*68 + r] = qa.x; Q0[(quad*4+1)*68 + r] = qa.y;
            Q0[(quad*4+2)*68 + r] = qa.z; Q0[(quad*4+3)*68 + r] = qa.w;
            Q1[(quad*4+0)*68 + r] = qb.x; Q1[(quad*4+1)*68 + r] = qb.y;
            Q1[(quad*4+2)*68 + r] = qb.z; Q1[(quad*4+3)*68 + r] = qb.w;
        }
        __syncthreads();

        float dA[4][4] = {}, dB[4][4] = {};
        #pragma unroll 4
        for (int kk = 0; kk < 64; ++kk) {
            float4 a0 = *(float4*)(Q0 + kk*68 + tr*4);
            float4 a1 = *(float4*)(Q1 + kk*68 + tr*4);
            float4 b  = *(float4*)(Kst + kk*68 + tc*4);
            dA[0][0] += a0.x*b.x; dA[0][1] += a0.x*b.y; dA[0][2] += a0.x*b.z; dA[0][3] += a0.x*b.w;
            dA[1][0] += a0.y*b.x; dA[1][1] += a0.y*b.y; dA[1][2] += a0.y*b.z; dA[1][3] += a0.y*b.w;
            dA[2][0] += a0.z*b.x; dA[2][1] += a0.z*b.y; dA[2][2] += a0.z*b.z; dA[2][3] += a0.z*b.w;
            dA[3][0] += a0.w*b.x; dA[3][1] += a0.w*b.y; dA[3][2] += a0.w*b.z; dA[3][3] += a0.w*b.w;
            dB[0][0] += a1.x*b.x; dB[0][1] += a1.x*b.y; dB[0][2] += a1.x*b.z; dB[0][3] += a1.x*b.w;
            dB[1][0] += a1.y*b.x; dB[1][1] += a1.y*b.y; dB[1][2] += a1.y*b.z; dB[1][3] += a1.y*b.w;
            dB[2][0] += a1.z*b.x; dB[2][1] += a1.z*b.y; dB[2][2] += a1.z*b.z; dB[2][3] += a1.z*b.w;
            dB[3][0] += a1.w*b.x; dB[3][1] += a1.w*b.y; dB[3][2] += a1.w*b.z; dB[3][3] += a1.w*b.w;
        }

        float bh0 = idx_bias[h0], bw0 = biw[h0];
        float bh1 = idx_bias[h1], bw1 = biw[h1];
        #pragma unroll
        for (int i = 0; i < 4; ++i) {
            const float* wrow = g_ix + (size_t)(q0 + tr * 4 + i) * NIW + OIW;
            float ws0 = 1.f / (1.f + expf(-(wrow[h0] + bw0)));
            float ws1 = 1.f / (1.f + expf(-(wrow[h1] + bw1)));
            #pragma unroll
            for (int j = 0; j < 4; ++j) {
                fin[i][j] += ws0 * (1.f / (1.f + expf(-(dA[i][j] * 0.125f + bh0))));
                fin[i][j] += ws1 * (1.f / (1.f + expf(-(dB[i][j] * 0.125f + bh1))));
            }
        }
    }

    #pragma unroll
    for (int i = 0; i < 4; ++i) {
        int qq = q0 + tr * 4 + i;
        #pragma unroll
        for (int j = 0; j < 4; ++j) {
            int jj = j0 + tc * 4 + j;
            if (jj <= qq) g_sc[(size_t)qq * T + jj] = fin[i][j];
        }
    }
}

// ---------------- fused attention: per-query exact top-128 (radix select) + softmax + PV ----------------
__global__ __launch_bounds__(256) void attn_kernel(const float* __restrict__ bog)
{
    const int q = blockIdx.x;
    const int n = q + 1;
    const int c = min(n, KSEL);
    const int tid = threadIdx.x;
    const int w = tid >> 5, lane = tid & 31;

    __shared__ int sidx[KSEL];
    __shared__ __align__(16) float qv[D];
    __shared__ float sp[NH][KSEL + 4];
    __shared__ unsigned sbits[T];
    __shared__ unsigned hist[256];
    __shared__ unsigned wtot[8], wsuf[8];
    __shared__ unsigned s_pref;
    __shared__ int s_need;
    __shared__ int wcnt, ecnt;
    __shared__ int eqi[256];

    const float* brow = g_big + (size_t)q * NB;
    qv[tid]       = brow[OQ + tid];
    qv[tid + 256] = brow[OQ + tid + 256];

    // ======== selection phase (was topk_kernel) ========
    if (n <= KSEL) {
        for (int j = tid; j < n; j += 256) sidx[j] = j;
        __syncthreads();
    } else {
        const float* row = g_sc + (size_t)q * T;
        for (int j = tid; j < n; j += 256)
            sbits[j] = __float_as_uint(row[j]);

        unsigned pref = 0;
        int need = KSEL;
        const int nIter = (n + 255) >> 8;

        for (int pass = 3; pass >= 0; --pass) {
            hist[tid] = 0;
            __syncthreads();
            const int sh = pass * 8;
            for (int it = 0; it < nIter; ++it) {
                int j = it * 256 + tid;
                unsigned b = (j < n) ? sbits[j] : 0u;
                bool ok = (j < n) && (pass == 3 || (b >> (sh + 8)) == pref);
                unsigned d = (b >> sh) & 255u;
                unsigned active = __ballot_sync(0xffffffffu, ok);
                if (ok) {
                    unsigned peers = __match_any_sync(active, d);
                    if (lane == __ffs(peers) - 1)
                        atomicAdd(&hist[d], (unsigned)__popc(peers));
                }
            }
            __syncthreads();

            unsigned hv = hist[tid];
            unsigned v = hv;
            #pragma unroll
            for (int off = 1; off < 32; off <<= 1) {
                unsigned t2 = __shfl_down_sync(0xffffffffu, v, off);
                if (lane < 32 - off) v += t2;
            }
            if (lane == 0) wtot[w] = v;
            __syncthreads();
            if (tid < 8) {
                unsigned s = 0;
                for (int w2 = tid + 1; w2 < 8; ++w2) s += wtot[w2];
                wsuf[tid] = s;
            }
            __syncthreads();
            unsigned incl  = v + wsuf[w];
            unsigned above = incl - hv;
            if (incl >= (unsigned)need && above < (unsigned)need) {
                s_pref = (pref << 8) | (unsigned)tid;
                s_need = need - (int)above;
            }
            __syncthreads();
            pref = s_pref;
            need = s_need;
        }

        const unsigned thr = pref;
        if (tid == 0) { wcnt = 0; ecnt = 0; }
        __syncthreads();
        for (int j = tid; j < n; j += 256) {
            unsigned b = sbits[j];
            if (b > thr) {
                int p = atomicAdd(&wcnt, 1);
                sidx[p] = j;
            } else if (b == thr) {
                int p = atomicAdd(&ecnt, 1);
                if (p < 256) eqi[p] = j;
            }
        }
        __syncthreads();
        if (tid == 0) {
            int E = min(ecnt, 256);
            for (int a = 1; a < E; ++a) {
                int v2 = eqi[a]; int b = a - 1;
                while (b >= 0 && eqi[b] > v2) { eqi[b + 1] = eqi[b]; --b; }
                eqi[b + 1] = v2;
            }
            int base = wcnt;
            for (int e2 = 0; e2 < need && e2 < E; ++e2)
                sidx[base + e2] = eqi[e2];
        }
        __syncthreads();
    }

    // ======== QK scores: warp per key, coalesced row loads ========
    {
        float4 q0 = *(const float4*)(qv + lane * 4);
        float4 q1 = *(const float4*)(qv + 128 + lane * 4);
        float4 q2 = *(const float4*)(qv + 256 + lane * 4);
        float4 q3 = *(const float4*)(qv + 384 + lane * 4);
        #pragma unroll 4
        for (int t = 0; t < 16; ++t) {
            int jj = w * 16 + t;
            if (jj < c) {
                const float4* kr = (const float4*)(g_k + (size_t)sidx[jj] * D);
                float4 k0 = kr[lane], k1 = kr[lane + 32], k2 = kr[lane + 64], k3 = kr[lane + 96];
                float p0 = q0.x*k0.x + q0.y*k0.y + q0.z*k0.z + q0.w*k0.w;
                float p1 = q1.x*k1.x + q1.y*k1.y + q1.z*k1.z + q1.w*k1.w;
                float p2 = q2.x*k2.x + q2.y*k2.y + q2.z*k2.z + q2.w*k2.w;
                float p3 = q3.x*k3.x + q3.y*k3.y + q3.z*k3.z + q3.w*k3.w;
                #pragma unroll
                for (int o = 1; o < 16; o <<= 1) {
                    p0 += __shfl_xor_sync(0xffffffffu, p0, o);
                    p1 += __shfl_xor_sync(0xffffffffu, p1, o);
                    p2 += __shfl_xor_sync(0xffffffffu, p2, o);
                    p3 += __shfl_xor_sync(0xffffffffu, p3, o);
                }
                if ((lane & 15) == 0) {
                    int hi = lane >> 4;
                    sp[0 + hi][jj] = p0 * 0.125f;
                    sp[2 + hi][jj] = p1 * 0.125f;
                    sp[4 + hi][jj] = p2 * 0.125f;
                    sp[6 + hi][jj] = p3 * 0.125f;
                }
            }
        }
    }
    __syncthreads();

    // ======== softmax (warp w = head w) ========
    {
        float m = -1e30f;
        for (int jj = lane; jj < c; jj += 32) m = fmaxf(m, sp[w][jj]);
        #pragma unroll
        for (int o = 16; o; o >>= 1) m = fmaxf(m, __shfl_xor_sync(0xffffffffu, m, o));
        float s = 0.f;
        for (int jj = lane; jj < c; jj += 32) { float e = expf(sp[w][jj] - m); sp[w][jj] = e; s += e; }
        #pragma unroll
        for (int o = 16; o; o >>= 1) s += __shfl_xor_sync(0xffffffffu, s, o);
        float inv = 1.f / s;
        for (int jj = lane; jj < c; jj += 32) sp[w][jj] *= inv;
    }
    __syncthreads();

    // ======== PV + output gate + fused bf16 split ========
    {
        const int e2 = tid;
        const int h = e2 >> 5;
        const float* spr = sp[h];
        const float2* vb = (const float2*)g_v;
        float2 acc = make_float2(0.f, 0.f);
        int jj = 0;
        for (; jj + 4 <= c; jj += 4) {
            float w0 = spr[jj+0], w1 = spr[jj+1], w2 = spr[jj+2], w3 = spr[jj+3];
            float2 v0 = vb[(size_t)sidx[jj+0] * 256 + e2];
            float2 v1 = vb[(size_t)sidx[jj+1] * 256 + e2];
            float2 v2 = vb[(size_t)sidx[jj+2] * 256 + e2];
            float2 v3 = vb[(size_t)sidx[jj+3] * 256 + e2];
            acc.x += w0 * v0.x + w1 * v1.x + w2 * v2.x + w3 * v3.x;
            acc.y += w0 * v0.y + w1 * v1.y + w2 * v2.y + w3 * v3.y;
        }
        for (; jj < c; ++jj) {
            float ww = spr[jj];
            float2 v = vb[(size_t)sidx[jj] * 256 + e2];
            acc.x += ww * v.x;
            acc.y += ww * v.y;
        }
        int e = e2 * 2;
        float g0 = 1.f / (1.f + expf(-(brow[OOG + e]     + bog[e])));
        float g1 = 1.f / (1.f + expf(-(brow[OOG + e + 1] + bog[e + 1])));
        float o0 = acc.x * g0, o1 = acc.y * g1;
        __nv_bfloat16 h0 = __float2bfloat16_rn(o0);
        __nv_bfloat16 h1 = __float2bfloat16_rn(o1);
        __nv_bfloat16 l0 = __float2bfloat16_rn(o0 - __bfloat162float(h0));
        __nv_bfloat16 l1 = __float2bfloat16_rn(o1 - __bfloat162float(h1));
        *(__nv_bfloat162*)(g_AoH + (size_t)q * D + e) = __nv_bfloat162(h0, h1);
        *(__nv_bfloat162*)(g_AoL + (size_t)q * D + e) = __nv_bfloat162(l0, l1);
    }
}

// ---------------- launch ----------------
extern "C" void kernel_launch(void* const* d_in, const int* in_sizes, int n_in,
                              void* d_out, int out_size)
{
    const float* x        = (const float*)d_in[0];
    const float* Wq       = (const float*)d_in[1];
    const float* Wk       = (const float*)d_in[2];
    const float* Wv       = (const float*)d_in[3];
    const float* Wo       = (const float*)d_in[4];
    const float* Wiq      = (const float*)d_in[5];
    const float* Wik      = (const float*)d_in[6];
    const float* Wiw      = (const float*)d_in[7];
    const float* biw      = (const float*)d_in[8];
    const float* idx_bias = (const float*)d_in[9];
    const float* Wvg      = (const float*)d_in[10];
    const float* bvg      = (const float*)d_in[11];
    const float* Wog      = (const float*)d_in[12];
    const float* bog      = (const float*)d_in[13];
    float* out = (float*)d_out;

    float *pbig, *pix, *pWi;
    __nv_bfloat16 *pAh, *pAl, *pBh, *pBl, *pAoH, *pAoL, *pWoH, *pWoL;
    cudaGetSymbolAddress((void**)&pbig, g_big);
    cudaGetSymbolAddress((void**)&pix,  g_ix);
    cudaGetSymbolAddress((void**)&pWi,  g_Wi);
    cudaGetSymbolAddress((void**)&pAh,  g_Ah);
    cudaGetSymbolAddress((void**)&pAl,  g_Al);
    cudaGetSymbolAddress((void**)&pBh,  g_Bh);
    cudaGetSymbolAddress((void**)&pBl,  g_Bl);
    cudaGetSymbolAddress((void**)&pAoH, g_AoH);
    cudaGetSymbolAddress((void**)&pAoL, g_AoL);
    cudaGetSymbolAddress((void**)&pWoH, g_WoH);
    cudaGetSymbolAddress((void**)&pWoL, g_WoL);

    cudaFuncSetAttribute(mma_gemm<3>, cudaFuncAttributeMaxDynamicSharedMemorySize, GEMM_SMEM);
    cudaFuncSetAttribute(mma_gemm<1>, cudaFuncAttributeMaxDynamicSharedMemorySize, GEMM_SMEM);
    cudaFuncSetAttribute(scores_kernel, cudaFuncAttributeMaxDynamicSharedMemorySize, SCW_SMEM);

    static cudaStream_t s1 = nullptr;
    static cudaEvent_t evF = nullptr, evJ = nullptr;
    if (s1 == nullptr) {
        cudaStreamCreateWithFlags(&s1, cudaStreamNonBlocking);
        cudaEventCreateWithFlags(&evF, cudaEventDisableTiming);
        cudaEventCreateWithFlags(&evJ, cudaEventDisableTiming);
    }

    dim3 th(256);

    // ---- fork: index/scores chain on s1 ----
    cudaEventRecord(evF, 0);
    cudaStreamWaitEvent(s1, evF, 0);

    packWi_kernel<<<(D*NIW + 255)/256, th, 0, s1>>>(Wiq, Wik, Wiw);
    split_kernel<<<(D*D + 255)/256, th, 0, s1>>>(Wo, pWoH, pWoL, D*D);   // consumed only after join
    sgemm_kernel<<<dim3(NIW/64, T/64), th, 0, s1>>>(x, pWi, pix, T, NIW, D);
    scores_kernel<<<dim3(32, 32), th, SCW_SMEM, s1>>>(idx_bias, biw);
    cudaEventRecord(evJ, s1);

    // ---- projection chain on the capture stream ----
    split_kernel<<<(T*D + 255)/256, th>>>(x, pAh, pAl, T*D);
    packB_kernel<<<(D*NB + 255)/256, th>>>(Wq, Wk, Wv, Wvg, Wog);
    rope_table_kernel<<<(T*32 + 255)/256, th>>>();
    // exact (split) part: Wq|Wk|Wv
    mma_gemm<3><<<dim3(NQKV/128, T/128), th, GEMM_SMEM>>>(pAh, pAl, pBh, pBl, pbig, T, NB, D, NQKV);
    // gate part: Wvg|Wog in plain bf16 (sigmoid-smoothed, validated margin)
    mma_gemm<1><<<dim3((NB-NQKV)/128, T/128), th, GEMM_SMEM>>>(pAh, pAl, pBh + NQKV, pBl + NQKV,
                                                               pbig + NQKV, T, NB, D, NB - NQKV);
    ew_kernel<<<T, th>>>(bvg);

    // ---- join, then fused select+attention + output projection ----
    cudaStreamWaitEvent(0, evJ, 0);
    attn_kernel<<<T, th>>>(bog);
    mma_gemm<3><<<dim3(D/128, T/128), th, GEMM_SMEM>>>(pAoH, pAoL, pWoH, pWoL, out, T, D, D, D);
}

// round 14
// speedup vs baseline: 1.7112x; 1.7112x over previous
#include <cuda_runtime.h>
#include <cuda_bf16.h>
#include <math.h>
#include <stdint.h>

#define T    2048
#define D    512
#define NH   8
#define DH   64
#define NI   4
#define DI   64
#define KSEL 128
#define NB   2560   // packed wide-GEMM N: Wq|Wk|Wv|Wvg|Wog = 5*512
#define NQKV 1536   // exact (3-term) portion
#define NIW  384    // packed index GEMM N: qi(256)|ki(64)|w(4)|pad

// offsets inside packed projection row
#define OQ   0
#define OK_  512
#define OV   1024
#define OVG  1536
#define OOG  2048
// offsets inside packed index row
#define OIQ  0
#define OIK  256
#define OIW  320

// ---------------- scratch (device globals; no allocation allowed) ----------------
__device__ __align__(256) float g_big[(size_t)T*NB];
__device__ __align__(256) float g_k [T*D];
__device__ __align__(256) float g_v [T*D];
__device__ __align__(256) float g_ix[(size_t)T*NIW];
__device__ __align__(256) float g_Wi[(size_t)D*NIW];
__device__ __align__(256) float g_sc[(size_t)T*T];
__device__ __align__(256) int   g_idx[T*KSEL];
__device__ __align__(256) float g_ao[T*D];
__device__ __align__(256) float g_cs[T*32];
__device__ __align__(256) float g_sn[T*32];

__device__ __align__(256) __nv_bfloat16 g_Ah[T*D],  g_Al[T*D];
__device__ __align__(256) __nv_bfloat16 g_Bh[(size_t)D*NB], g_Bl[(size_t)D*NB];
__device__ __align__(256) __nv_bfloat16 g_AoH[T*D], g_AoL[T*D];
__device__ __align__(256) __nv_bfloat16 g_WoH[D*D], g_WoL[D*D];

// ---------------- tensor-core helpers ----------------
__device__ __forceinline__ void cpa16(void* dst, const void* src) {
    uint32_t d = (uint32_t)__cvta_generic_to_shared(dst);
    asm volatile("cp.async.cg.shared.global [%0],[%1],16;\n" :: "r"(d), "l"(src));
}
__device__ __forceinline__ void cp_commit() { asm volatile("cp.async.commit_group;\n"); }

__device__ __forceinline__ void ldsm_x4(uint32_t* r, const void* p) {
    uint32_t a = (uint32_t)__cvta_generic_to_shared(p);
    asm volatile("ldmatrix.sync.aligned.m8n8.x4.shared.b16 {%0,%1,%2,%3},[%4];"
                 : "=r"(r[0]), "=r"(r[1]), "=r"(r[2]), "=r"(r[3]) : "r"(a));
}
__device__ __forceinline__ void ldsm_x2t(uint32_t* r, const void* p) {
    uint32_t a = (uint32_t)__cvta_generic_to_shared(p);
    asm volatile("ldmatrix.sync.aligned.m8n8.x2.trans.shared.b16 {%0,%1},[%2];"
                 : "=r"(r[0]), "=r"(r[1]) : "r"(a));
}
__device__ __forceinline__ void mma16816(float* c, const uint32_t* a, const uint32_t* b) {
    asm volatile("mma.sync.aligned.m16n8k16.row.col.f32.bf16.bf16.f32 "
                 "{%0,%1,%2,%3},{%4,%5,%6,%7},{%8,%9},{%0,%1,%2,%3};"
                 : "+f"(c[0]), "+f"(c[1]), "+f"(c[2]), "+f"(c[3])
                 : "r"(a[0]), "r"(a[1]), "r"(a[2]), "r"(a[3]), "r"(b[0]), "r"(b[1]));
}

// ---------------- split fp32 -> (bf16 hi, bf16 lo) ----------------
__global__ __launch_bounds__(256) void split_kernel(
    const float* __restrict__ src, __nv_bfloat16* __restrict__ h,
    __nv_bfloat16* __restrict__ l, int n)
{
    int i = blockIdx.x * 256 + threadIdx.x;
    if (i < n) {
        float f = src[i];
        __nv_bfloat16 hh = __float2bfloat16_rn(f);
        float r = f - __bfloat162float(hh);
        h[i] = hh;
        l[i] = __float2bfloat16_rn(r);
    }
}

// ---------------- pack 5 weight matrices into B[512][NB] (split bf16) ----------------
__global__ __launch_bounds__(256) void packB_kernel(
    const float* __restrict__ Wq, const float* __restrict__ Wk,
    const float* __restrict__ Wv, const float* __restrict__ Wvg,
    const float* __restrict__ Wog)
{
    int i = blockIdx.x * 256 + threadIdx.x;
    if (i >= D * NB) return;
    int k = i / NB, c = i % NB;
    float f;
    if      (c < 1024) f = (c < 512)  ? Wq [k*512 + c]        : Wk [k*512 + c - 512];
    else if (c < 2048) f = (c < 1536) ? Wv [k*512 + c - 1024] : Wvg[k*512 + c - 1536];
    else               f = Wog[k*512 + c - 2048];
    __nv_bfloat16 hh = __float2bfloat16_rn(f);
    g_Bh[i] = hh;
    g_Bl[i] = __float2bfloat16_rn(f - __bfloat162float(hh));
}

// ---------------- pack index weights (fp32, exact) ----------------
__global__ __launch_bounds__(256) void packWi_kernel(
    const float* __restrict__ Wiq, const float* __restrict__ Wik,
    const float* __restrict__ Wiw)
{
    int i = blockIdx.x * 256 + threadIdx.x;
    if (i >= D * NIW) return;
    int k = i / NIW, c = i % NIW;
    float f;
    if      (c < 256) f = Wiq[k*256 + c];
    else if (c < 320) f = Wik[k*64  + c - 256];
    else if (c < 324) f = Wiw[k*4   + c - 320];
    else              f = 0.f;
    g_Wi[i] = f;
}

// ---------------- split-bf16 tensor-core GEMM (TERMS=3 exact / TERMS=1 plain bf16) ----------------
#define SA_STRIDE 40
#define SB_STRIDE 136
#define SA_SZ (128*SA_STRIDE)
#define SB_SZ (32*SB_STRIDE)
#define GEMM_SMEM ((2*2*SA_SZ + 2*2*SB_SZ)*2)

template<int TERMS>
__global__ __launch_bounds__(256) void mma_gemm(
    const __nv_bfloat16* __restrict__ Ah, const __nv_bfloat16* __restrict__ Al,
    const __nv_bfloat16* __restrict__ Bh, const __nv_bfloat16* __restrict__ Bl,
    float* __restrict__ C, int M, int N, int K)
{
    extern __shared__ __align__(16) char smem_raw[];
    __nv_bfloat16* sA = (__nv_bfloat16*)smem_raw;
    __nv_bfloat16* sB = (__nv_bfloat16*)(smem_raw + 2*2*SA_SZ*2);
    const int tid = threadIdx.x;
    const int m0 = blockIdx.y * 128, n0 = blockIdx.x * 128;

    const int wid = tid >> 5, lane = tid & 31;
    const int m0w = (wid & 1) * 64, n0w = (wid >> 1) * 32;
    const int a_row = (lane & 15);
    const int a_koff = (lane >> 4) * 8;
    const int l15 = lane & 15;
    const int b_krow = (l15 & 7) + (l15 >> 3) * 8;

    float acc[4][4][4];
    #pragma unroll
    for (int i = 0; i < 4; ++i)
        #pragma unroll
        for (int j = 0; j < 4; ++j)
            #pragma unroll
            for (int r = 0; r < 4; ++r) acc[i][j][r] = 0.f;

    auto load_stage = [&](int st, int k0) {
        __nv_bfloat16* aH = sA + (st*2+0)*SA_SZ;
        __nv_bfloat16* aL = sA + (st*2+1)*SA_SZ;
        __nv_bfloat16* bH = sB + (st*2+0)*SB_SZ;
        __nv_bfloat16* bL = sB + (st*2+1)*SB_SZ;
        #pragma unroll
        for (int i = 0; i < 2; ++i) {
            int c = tid + i * 256;
            int r = c >> 2, cc = (c & 3) * 8;
            cpa16(aH + r*SA_STRIDE + cc, Ah + (size_t)(m0 + r) * K + k0 + cc);
            if (TERMS == 3)
                cpa16(aL + r*SA_STRIDE + cc, Al + (size_t)(m0 + r) * K + k0 + cc);
            int rb = c >> 4, cb = (c & 15) * 8;
            cpa16(bH + rb*SB_STRIDE + cb, Bh + (size_t)(k0 + rb) * N + n0 + cb);
            if (TERMS == 3)
                cpa16(bL + rb*SB_STRIDE + cb, Bl + (size_t)(k0 + rb) * N + n0 + cb);
        }
        cp_commit();
    };

    load_stage(0, 0);
    const int KT = K / 32;
    for (int kt = 0; kt < KT; ++kt) {
        if (kt + 1 < KT) {
            load_stage((kt + 1) & 1, (kt + 1) * 32);
            asm volatile("cp.async.wait_group 1;\n");
        } else {
            asm volatile("cp.async.wait_group 0;\n");
        }
        __syncthreads();

        const int st = kt & 1;
        const __nv_bfloat16* aP[2] = { sA + (st*2+0)*SA_SZ, sA + (st*2+1)*SA_SZ };
        const __nv_bfloat16* bP[2] = { sB + (st*2+0)*SB_SZ, sB + (st*2+1)*SB_SZ };

        #pragma unroll
        for (int kk = 0; kk < 32; kk += 16) {
            uint32_t af[2][4][4];
            uint32_t bf[2][4][2];
            #pragma unroll
            for (int p = 0; p < (TERMS == 3 ? 2 : 1); ++p) {
                #pragma unroll
                for (int mt = 0; mt < 4; ++mt)
                    ldsm_x4(af[p][mt], aP[p] + (m0w + mt*16 + a_row)*SA_STRIDE + kk + a_koff);
                #pragma unroll
                for (int nt = 0; nt < 4; ++nt)
                    ldsm_x2t(bf[p][nt], bP[p] + (kk + b_krow)*SB_STRIDE + n0w + nt*8);
            }
            #pragma unroll
            for (int mt = 0; mt < 4; ++mt)
                #pragma unroll
                for (int nt = 0; nt < 4; ++nt) {
                    mma16816(acc[mt][nt], af[0][mt], bf[0][nt]);
                    if (TERMS == 3) {
                        mma16816(acc[mt][nt], af[0][mt], bf[1][nt]);
                        mma16816(acc[mt][nt], af[1][mt], bf[0][nt]);
                    }
                }
        }
        __syncthreads();
    }

    #pragma unroll
    for (int mt = 0; mt < 4; ++mt) {
        int row = m0 + m0w + mt*16 + (lane >> 2);
        #pragma unroll
        for (int nt = 0; nt < 4; ++nt) {
            int col = n0 + n0w + nt*8 + (lane & 3)*2;
            *(float2*)(C + (size_t)row * N + col)       = make_float2(acc[mt][nt][0], acc[mt][nt][1]);
            *(float2*)(C + (size_t)(row + 8) * N + col) = make_float2(acc[mt][nt][2], acc[mt][nt][3]);
        }
    }
}

// ---------------- fp32 SIMT SGEMM (exact path for top-k ranking inputs) ----------------
__global__ __launch_bounds__(256) void sgemm_kernel(
    const float* __restrict__ A, const float* __restrict__ B,
    float* __restrict__ C, int M, int N, int K)
{
    __shared__ float Ast[16][68];
    __shared__ float Bs [16][64];
    const int tid = threadIdx.x;
    const int m0 = blockIdx.y * 64, n0 = blockIdx.x * 64;
    const int tr = tid >> 4, tc = tid & 15;
    const int arow = tid >> 2, akq = tid & 3;
    const int brow = tid >> 4, bnq = tid & 15;

    float acc[4][4] = {};

    for (int k0 = 0; k0 < K; k0 += 16) {
        float4 av = *(const float4*)(A + (size_t)(m0 + arow) * K + k0 + akq * 4);
        Ast[akq*4+0][arow] = av.x;
        Ast[akq*4+1][arow] = av.y;
        Ast[akq*4+2][arow] = av.z;
        Ast[akq*4+3][arow] = av.w;

        float4 bv = *(const float4*)(B + (size_t)(k0 + brow) * N + n0 + bnq * 4);
        *(float4*)&Bs[brow][bnq * 4] = bv;
        __syncthreads();

        #pragma unroll
        for (int kk = 0; kk < 16; ++kk) {
            float4 a = *(float4*)&Ast[kk][tr * 4];
            float4 b = *(float4*)&Bs [kk][tc * 4];
            acc[0][0] += a.x * b.x; acc[0][1] += a.x * b.y; acc[0][2] += a.x * b.z; acc[0][3] += a.x * b.w;
            acc[1][0] += a.y * b.x; acc[1][1] += a.y * b.y; acc[1][2] += a.y * b.z; acc[1][3] += a.y * b.w;
            acc[2][0] += a.z * b.x; acc[2][1] += a.z * b.y; acc[2][2] += a.z * b.z; acc[2][3] += a.z * b.w;
            acc[3][0] += a.w * b.x; acc[3][1] += a.w * b.y; acc[3][2] += a.w * b.z; acc[3][3] += a.w * b.w;
        }
        __syncthreads();
    }

    #pragma unroll
    for (int i = 0; i < 4; ++i) {
        int r = m0 + tr * 4 + i;
        #pragma unroll
        for (int j = 0; j < 4; ++j)
            C[(size_t)r * N + n0 + tc * 4 + j] = acc[i][j];
    }
}

// ---------------- RoPE cos/sin table (fp32, matches reference) ----------------
__global__ __launch_bounds__(256) void rope_table_kernel()
{
    int i = blockIdx.x * 256 + threadIdx.x;
    if (i >= T * 32) return;
    int t = i >> 5, jm = i & 31;
    float invf = powf(10000.f, -(float)(2 * jm) / 64.f);
    float ph = (float)t * invf;
    float s, c;
    sincosf(ph, &s, &c);
    g_cs[i] = c;
    g_sn[i] = s;
}

// ---------------- RoPE(q,k) + v*sigmoid(vg+bvg) ----------------
__global__ __launch_bounds__(256) void ew_kernel(const float* __restrict__ bvg)
{
    int t = blockIdx.x, tid = threadIdx.x;
    float* row = g_big + (size_t)t * NB;
    __shared__ float sq[D], sk[D];
    sq[tid]       = row[OQ + tid];
    sq[tid + 256] = row[OQ + tid + 256];
    sk[tid]       = row[OK_ + tid];
    sk[tid + 256] = row[OK_ + tid + 256];
    __syncthreads();
    #pragma unroll
    for (int it = 0; it < 2; ++it) {
        int e = tid + it * 256;
        int j = e & 63, jm = j & 31;
        float cc = g_cs[t * 32 + jm], ss = g_sn[t * 32 + jm];
        float rq = (j < 32) ? -sq[e + 32] : sq[e - 32];
        float rk = (j < 32) ? -sk[e + 32] : sk[e - 32];
        row[OQ + e] = sq[e] * cc + rq * ss;
        g_k[(size_t)t * D + e] = sk[e] * cc + rk * ss;
        float vv = row[OV + e], vg = row[OVG + e];
        g_v[(size_t)t * D + e] = vv * (1.f / (1.f + expf(-(vg + bvg[e]))));
    }
}

// ---------------- index scores (64x64 tile, 4x4/thread — R7 measured version) ----------------
__global__ __launch_bounds__(256) void scores_kernel(const float* __restrict__ idx_bias,
                                                     const float* __restrict__ biw)
{
    const int q0 = blockIdx.y * 64, j0 = blockIdx.x * 64;
    if (j0 > q0 + 63) return;
    __shared__ float Qst[64][68];
    __shared__ float Kst[64][68];
    const int tid = threadIdx.x;
    const int tr = tid >> 4, tc = tid & 15;

    #pragma unroll
    for (int it = 0; it < 4; ++it) {
        int e = tid + it * 256;
        int r = e >> 4, quad = e & 15;
        float4 kv = *(const float4*)(g_ix + (size_t)(j0 + r) * NIW + OIK + quad * 4);
        Kst[quad*4+0][r] = kv.x; Kst[quad*4+1][r] = kv.y;
        Kst[quad*4+2][r] = kv.z; Kst[quad*4+3][r] = kv.w;
    }

    float fin[4][4] = {};
    for (int h = 0; h < NI; ++h) {
        if (h) __syncthreads();
        #pragma unroll
        for (int it = 0; it < 4; ++it) {
            int e = tid + it * 256;
            int r = e >> 4, quad = e & 15;
            float4 qv = *(const float4*)(g_ix + (size_t)(q0 + r) * NIW + OIQ + h * DI + quad * 4);
            Qst[quad*4+0][r] = qv.x; Qst[quad*4+1][r] = qv.y;
            Qst[quad*4+2][r] = qv.z; Qst[quad*4+3][r] = qv.w;
        }
        __syncthreads();

        float d4[4][4] = {};
        #pragma unroll
        for (int kk = 0; kk < 64; ++kk) {
            float4 a = *(float4*)&Qst[kk][tr * 4];
            float4 b = *(float4*)&Kst[kk][tc * 4];
            d4[0][0] += a.x * b.x; d4[0][1] += a.x * b.y; d4[0][2] += a.x * b.z; d4[0][3] += a.x * b.w;
            d4[1][0] += a.y * b.x; d4[1][1] += a.y * b.y; d4[1][2] += a.y * b.z; d4[1][3] += a.y * b.w;
            d4[2][0] += a.z * b.x; d4[2][1] += a.z * b.y; d4[2][2] += a.z * b.z; d4[2][3] += a.z * b.w;
            d4[3][0] += a.w * b.x; d4[3][1] += a.w * b.y; d4[3][2] += a.w * b.z; d4[3][3] += a.w * b.w;
        }
        float bh = idx_bias[h];
        float bw = biw[h];
        #pragma unroll
        for (int i = 0; i < 4; ++i) {
            float wr = g_ix[(size_t)(q0 + tr * 4 + i) * NIW + OIW + h];
            float ws = 1.f / (1.f + expf(-(wr + bw)));
            #pragma unroll
            for (int j = 0; j < 4; ++j)
                fin[i][j] += ws * (1.f / (1.f + expf(-(d4[i][j] * 0.125f + bh))));
        }
    }

    #pragma unroll
    for (int i = 0; i < 4; ++i) {
        int qq = q0 + tr * 4 + i;
        #pragma unroll
        for (int j = 0; j < 4; ++j) {
            int jj = j0 + tc * 4 + j;
            if (jj <= qq) g_sc[(size_t)qq * T + jj] = fin[i][j];
        }
    }
}

// ---------------- exact top-128: radix select (R7 measured version) ----------------
__global__ __launch_bounds__(256) void topk_kernel()
{
    const int q = blockIdx.x;
    const int n = q + 1;
    const int tid = threadIdx.x;
    const int lane = tid & 31;
    const int wid = tid >> 5;

    if (n <= KSEL) {
        for (int j = tid; j < n; j += 256) g_idx[q * KSEL + j] = j;
        return;
    }

    __shared__ unsigned sbits[T];
    const float* row = g_sc + (size_t)q * T;
    for (int j = tid; j < n; j += 256)
        sbits[j] = __float_as_uint(row[j]);

    __shared__ unsigned hist[256];
    __shared__ unsigned wtot[8], wsuf[8];
    __shared__ unsigned s_pref;
    __shared__ int s_need;
    unsigned pref = 0;
    int need = KSEL;
    const int nIter = (n + 255) >> 8;

    for (int pass = 3; pass >= 0; --pass) {
        hist[tid] = 0;
        __syncthreads();
        const int sh = pass * 8;
        for (int it = 0; it < nIter; ++it) {
            int j = it * 256 + tid;
            unsigned b = (j < n) ? sbits[j] : 0u;
            bool ok = (j < n) && (pass == 3 || (b >> (sh + 8)) == pref);
            unsigned d = (b >> sh) & 255u;
            unsigned active = __ballot_sync(0xffffffffu, ok);
            if (ok) {
                unsigned peers = __match_any_sync(active, d);
                if (lane == __ffs(peers) - 1)
                    atomicAdd(&hist[d], (unsigned)__popc(peers));
            }
        }
        __syncthreads();

        unsigned hv = hist[tid];
        unsigned v = hv;
        #pragma unroll
        for (int off = 1; off < 32; off <<= 1) {
            unsigned t2 = __shfl_down_sync(0xffffffffu, v, off);
            if (lane < 32 - off) v += t2;
        }
        if (lane == 0) wtot[wid] = v;
        __syncthreads();
        if (tid < 8) {
            unsigned s = 0;
            for (int w2 = tid + 1; w2 < 8; ++w2) s += wtot[w2];
            wsuf[tid] = s;
        }
        __syncthreads();
        unsigned incl  = v + wsuf[wid];
        unsigned above = incl - hv;
        if (incl >= (unsigned)need && above < (unsigned)need) {
            s_pref = (pref << 8) | (unsigned)tid;
            s_need = need - (int)above;
        }
        __syncthreads();
        pref = s_pref;
        need = s_need;
    }

    const unsigned thr = pref;
    __shared__ int wcnt;
    __shared__ int eqi[256];
    __shared__ int ecnt;
    if (tid == 0) { wcnt = 0; ecnt = 0; }
    __syncthreads();
    for (int j = tid; j < n; j += 256) {
        unsigned b = sbits[j];
        if (b > thr) {
            int p = atomicAdd(&wcnt, 1);
            g_idx[q * KSEL + p] = j;
        } else if (b == thr) {
            int p = atomicAdd(&ecnt, 1);
            if (p < 256) eqi[p] = j;
        }
    }
    __syncthreads();
    if (tid == 0) {
        int E = min(ecnt, 256);
        for (int a = 1; a < E; ++a) {
            int v2 = eqi[a]; int b = a - 1;
            while (b >= 0 && eqi[b] > v2) { eqi[b + 1] = eqi[b]; --b; }
            eqi[b + 1] = v2;
        }
        int base = wcnt;
        for (int e2 = 0; e2 < need && e2 < E; ++e2)
            g_idx[q * KSEL + base + e2] = eqi[e2];
    }
}

// ---------------- sparse attention (warp-per-key QK — R7 measured version) ----------------
__global__ __launch_bounds__(256) void attn_kernel(const float* __restrict__ bog)
{
    const int q = blockIdx.x;
    const int c = min(q + 1, KSEL);
    __shared__ int sidx[KSEL];
    __shared__ __align__(16) float qv[D];
    __shared__ float sp[NH][KSEL + 4];
    const int tid = threadIdx.x;
    const int w = tid >> 5, lane = tid & 31;
    const float* brow = g_big + (size_t)q * NB;

    if (tid < c) sidx[tid] = g_idx[q * KSEL + tid];
    qv[tid]       = brow[OQ + tid];
    qv[tid + 256] = brow[OQ + tid + 256];
    __syncthreads();

    {
        float4 q0 = *(const float4*)(qv + lane * 4);
        float4 q1 = *(const float4*)(qv + 128 + lane * 4);
        float4 q2 = *(const float4*)(qv + 256 + lane * 4);
        float4 q3 = *(const float4*)(qv + 384 + lane * 4);
        #pragma unroll 4
        for (int t = 0; t < 16; ++t) {
            int jj = w * 16 + t;
            if (jj < c) {
                const float4* kr = (const float4*)(g_k + (size_t)sidx[jj] * D);
                float4 k0 = kr[lane], k1 = kr[lane + 32], k2 = kr[lane + 64], k3 = kr[lane + 96];
                float p0 = q0.x*k0.x + q0.y*k0.y + q0.z*k0.z + q0.w*k0.w;
                float p1 = q1.x*k1.x + q1.y*k1.y + q1.z*k1.z + q1.w*k1.w;
                float p2 = q2.x*k2.x + q2.y*k2.y + q2.z*k2.z + q2.w*k2.w;
                float p3 = q3.x*k3.x + q3.y*k3.y + q3.z*k3.z + q3.w*k3.w;
                #pragma unroll
                for (int o = 1; o < 16; o <<= 1) {
                    p0 += __shfl_xor_sync(0xffffffffu, p0, o);
                    p1 += __shfl_xor_sync(0xffffffffu, p1, o);
                    p2 += __shfl_xor_sync(0xffffffffu, p2, o);
                    p3 += __shfl_xor_sync(0xffffffffu, p3, o);
                }
                if ((lane & 15) == 0) {
                    int hi = lane >> 4;
                    sp[0 + hi][jj] = p0 * 0.125f;
                    sp[2 + hi][jj] = p1 * 0.125f;
                    sp[4 + hi][jj] = p2 * 0.125f;
                    sp[6 + hi][jj] = p3 * 0.125f;
                }
            }
        }
    }
    __syncthreads();

    {
        float m = -1e30f;
        for (int jj = lane; jj < c; jj += 32) m = fmaxf(m, sp[w][jj]);
        #pragma unroll
        for (int o = 16; o; o >>= 1) m = fmaxf(m, __shfl_xor_sync(0xffffffffu, m, o));
        float s = 0.f;
        for (int jj = lane; jj < c; jj += 32) { float e = expf(sp[w][jj] - m); sp[w][jj] = e; s += e; }
        #pragma unroll
        for (int o = 16; o; o >>= 1) s += __shfl_xor_sync(0xffffffffu, s, o);
        float inv = 1.f / s;
        for (int jj = lane; jj < c; jj += 32) sp[w][jj] *= inv;
    }
    __syncthreads();

    {
        const int e2 = tid;
        const int h = e2 >> 5;
        const float* spr = sp[h];
        const float2* vb = (const float2*)g_v;
        float2 acc = make_float2(0.f, 0.f);
        int jj = 0;
        for (; jj + 4 <= c; jj += 4) {
            float w0 = spr[jj+0], w1 = spr[jj+1], w2 = spr[jj+2], w3 = spr[jj+3];
            float2 v0 = vb[(size_t)sidx[jj+0] * 256 + e2];
            float2 v1 = vb[(size_t)sidx[jj+1] * 256 + e2];
            float2 v2 = vb[(size_t)sidx[jj+2] * 256 + e2];
            float2 v3 = vb[(size_t)sidx[jj+3] * 256 + e2];
            acc.x += w0 * v0.x + w1 * v1.x + w2 * v2.x + w3 * v3.x;
            acc.y += w0 * v0.y + w1 * v1.y + w2 * v2.y + w3 * v3.y;
        }
        for (; jj < c; ++jj) {
            float ww = spr[jj];
            float2 v = vb[(size_t)sidx[jj] * 256 + e2];
            acc.x += ww * v.x;
            acc.y += ww * v.y;
        }
        int e = e2 * 2;
        float g0 = 1.f / (1.f + expf(-(brow[OOG + e]     + bog[e])));
        float g1 = 1.f / (1.f + expf(-(brow[OOG + e + 1] + bog[e + 1])));
        *(float2*)(g_ao + (size_t)q * D + e) = make_float2(acc.x * g0, acc.y * g1);
    }
}

// ---------------- launch ----------------
extern "C" void kernel_launch(void* const* d_in, const int* in_sizes, int n_in,
                              void* d_out, int out_size)
{
    const float* x        = (const float*)d_in[0];
    const float* Wq       = (const float*)d_in[1];
    const float* Wk       = (const float*)d_in[2];
    const float* Wv       = (const float*)d_in[3];
    const float* Wo       = (const float*)d_in[4];
    const float* Wiq      = (const float*)d_in[5];
    const float* Wik      = (const float*)d_in[6];
    const float* Wiw      = (const float*)d_in[7];
    const float* biw      = (const float*)d_in[8];
    const float* idx_bias = (const float*)d_in[9];
    const float* Wvg      = (const float*)d_in[10];
    const float* bvg      = (const float*)d_in[11];
    const float* Wog      = (const float*)d_in[12];
    const float* bog      = (const float*)d_in[13];
    float* out = (float*)d_out;

    float *pbig, *pao, *pix, *pWi;
    __nv_bfloat16 *pAh, *pAl, *pBh, *pBl, *pAoH, *pAoL, *pWoH, *pWoL;
    cudaGetSymbolAddress((void**)&pbig, g_big);
    cudaGetSymbolAddress((void**)&pao,  g_ao);
    cudaGetSymbolAddress((void**)&pix,  g_ix);
    cudaGetSymbolAddress((void**)&pWi,  g_Wi);
    cudaGetSymbolAddress((void**)&pAh,  g_Ah);
    cudaGetSymbolAddress((void**)&pAl,  g_Al);
    cudaGetSymbolAddress((void**)&pBh,  g_Bh);
    cudaGetSymbolAddress((void**)&pBl,  g_Bl);
    cudaGetSymbolAddress((void**)&pAoH, g_AoH);
    cudaGetSymbolAddress((void**)&pAoL, g_AoL);
    cudaGetSymbolAddress((void**)&pWoH, g_WoH);
    cudaGetSymbolAddress((void**)&pWoL, g_WoL);

    cudaFuncSetAttribute(mma_gemm<3>, cudaFuncAttributeMaxDynamicSharedMemorySize, GEMM_SMEM);
    cudaFuncSetAttribute(mma_gemm<1>, cudaFuncAttributeMaxDynamicSharedMemorySize, GEMM_SMEM);

    static cudaStream_t s1 = nullptr;
    static cudaEvent_t evF = nullptr, evJ = nullptr;
    if (s1 == nullptr) {
        cudaStreamCreateWithFlags(&s1, cudaStreamNonBlocking);
        cudaEventCreateWithFlags(&evF, cudaEventDisableTiming);
        cudaEventCreateWithFlags(&evJ, cudaEventDisableTiming);
    }

    dim3 th(256);

    // ---- fork: index/top-k chain on s1 ----
    cudaEventRecord(evF, 0);
    cudaStreamWaitEvent(s1, evF, 0);

    packWi_kernel<<<(D*NIW + 255)/256, th, 0, s1>>>(Wiq, Wik, Wiw);
    sgemm_kernel<<<dim3(NIW/64, T/64), th, 0, s1>>>(x, pWi, pix, T, NIW, D);
    scores_kernel<<<dim3(32, 32), th, 0, s1>>>(idx_bias, biw);
    topk_kernel<<<T, th, 0, s1>>>();
    cudaEventRecord(evJ, s1);

    // ---- projection chain on the capture stream ----
    split_kernel<<<(T*D + 255)/256, th>>>(x, pAh, pAl, T*D);
    packB_kernel<<<(D*NB + 255)/256, th>>>(Wq, Wk, Wv, Wvg, Wog);
    split_kernel<<<(D*D + 255)/256, th>>>(Wo, pWoH, pWoL, D*D);
    rope_table_kernel<<<(T*32 + 255)/256, th>>>();
    // exact (3-term) part: Wq|Wk|Wv
    mma_gemm<3><<<dim3(NQKV/128, T/128), th, GEMM_SMEM>>>(pAh, pAl, pBh, pBl, pbig, T, NB, D);
    // gate part: Wvg|Wog plain bf16 (sigmoid-smoothed; R12-validated 5.1e-4)
    mma_gemm<1><<<dim3((NB-NQKV)/128, T/128), th, GEMM_SMEM>>>(pAh, pAl, pBh + NQKV, pBl + NQKV,
                                                               pbig + NQKV, T, NB, D);
    ew_kernel<<<T, th>>>(bvg);

    // ---- join, then attention + output projection ----
    cudaStreamWaitEvent(0, evJ, 0);
    attn_kernel<<<T, th>>>(bog);
    split_kernel<<<(T*D + 255)/256, th>>>(pao, pAoH, pAoL, T*D);
    mma_gemm<3><<<dim3(D/128, T/128), th, GEMM_SMEM>>>(pAoH, pAoL, pWoH, pWoL, out, T, D, D);
}

// round 15
// speedup vs baseline: 1.7407x; 1.0173x over previous
#include <cuda_runtime.h>
#include <cuda_bf16.h>
#include <math.h>
#include <stdint.h>

#define T    2048
#define D    512
#define NH   8
#define DH   64
#define NI   4
#define DI   64
#define KSEL 128
#define NB   2560   // packed wide-GEMM N: Wq|Wk|Wv|Wvg|Wog = 5*512
#define NQKV 1536   // exact (3-term) portion
#define NIW  384    // packed index GEMM N: qi(256)|ki(64)|w(4)|pad

// offsets inside packed projection row
#define OQ   0
#define OK_  512
#define OV   1024
#define OVG  1536
#define OOG  2048
// offsets inside packed index row
#define OIQ  0
#define OIK  256
#define OIW  320

// ---------------- scratch (device globals; no allocation allowed) ----------------
__device__ __align__(256) float g_big[(size_t)T*NB];
__device__ __align__(256) float g_k [T*D];
__device__ __align__(256) float g_v [T*D];
__device__ __align__(256) float g_ix[(size_t)T*NIW];
__device__ __align__(256) float g_Wi[(size_t)D*NIW];
__device__ __align__(256) float g_sc[(size_t)T*T];
__device__ __align__(256) int   g_idx[T*KSEL];
__device__ __align__(256) float g_ao[T*D];
__device__ __align__(256) float g_cs[T*32];
__device__ __align__(256) float g_sn[T*32];

__device__ __align__(256) __nv_bfloat16 g_Ah[T*D],  g_Al[T*D];
__device__ __align__(256) __nv_bfloat16 g_Bh[(size_t)D*NB], g_Bl[(size_t)D*NB];
__device__ __align__(256) __nv_bfloat16 g_AoH[T*D], g_AoL[T*D];
__device__ __align__(256) __nv_bfloat16 g_WoH[D*D], g_WoL[D*D];

// ---------------- tensor-core helpers ----------------
__device__ __forceinline__ void cpa16(void* dst, const void* src) {
    uint32_t d = (uint32_t)__cvta_generic_to_shared(dst);
    asm volatile("cp.async.cg.shared.global [%0],[%1],16;\n" :: "r"(d), "l"(src));
}
__device__ __forceinline__ void cp_commit() { asm volatile("cp.async.commit_group;\n"); }

__device__ __forceinline__ void ldsm_x4(uint32_t* r, const void* p) {
    uint32_t a = (uint32_t)__cvta_generic_to_shared(p);
    asm volatile("ldmatrix.sync.aligned.m8n8.x4.shared.b16 {%0,%1,%2,%3},[%4];"
                 : "=r"(r[0]), "=r"(r[1]), "=r"(r[2]), "=r"(r[3]) : "r"(a));
}
__device__ __forceinline__ void ldsm_x2t(uint32_t* r, const void* p) {
    uint32_t a = (uint32_t)__cvta_generic_to_shared(p);
    asm volatile("ldmatrix.sync.aligned.m8n8.x2.trans.shared.b16 {%0,%1},[%2];"
                 : "=r"(r[0]), "=r"(r[1]) : "r"(a));
}
__device__ __forceinline__ void mma16816(float* c, const uint32_t* a, const uint32_t* b) {
    asm volatile("mma.sync.aligned.m16n8k16.row.col.f32.bf16.bf16.f32 "
                 "{%0,%1,%2,%3},{%4,%5,%6,%7},{%8,%9},{%0,%1,%2,%3};"
                 : "+f"(c[0]), "+f"(c[1]), "+f"(c[2]), "+f"(c[3])
                 : "r"(a[0]), "r"(a[1]), "r"(a[2]), "r"(a[3]), "r"(b[0]), "r"(b[1]));
}

// ---------------- split fp32 -> (bf16 hi, bf16 lo) ----------------
__global__ __launch_bounds__(256) void split_kernel(
    const float* __restrict__ src, __nv_bfloat16* __restrict__ h,
    __nv_bfloat16* __restrict__ l, int n)
{
    int i = blockIdx.x * 256 + threadIdx.x;
    if (i < n) {
        float f = src[i];
        __nv_bfloat16 hh = __float2bfloat16_rn(f);
        float r = f - __bfloat162float(hh);
        h[i] = hh;
        l[i] = __float2bfloat16_rn(r);
    }
}

// ---------------- pack 5 weight matrices into B[512][NB] (split bf16) ----------------
__global__ __launch_bounds__(256) void packB_kernel(
    const float* __restrict__ Wq, const float* __restrict__ Wk,
    const float* __restrict__ Wv, const float* __restrict__ Wvg,
    const float* __restrict__ Wog)
{
    int i = blockIdx.x * 256 + threadIdx.x;
    if (i >= D * NB) return;
    int k = i / NB, c = i % NB;
    float f;
    if      (c < 1024) f = (c < 512)  ? Wq [k*512 + c]        : Wk [k*512 + c - 512];
    else if (c < 2048) f = (c < 1536) ? Wv [k*512 + c - 1024] : Wvg[k*512 + c - 1536];
    else               f = Wog[k*512 + c - 2048];
    __nv_bfloat16 hh = __float2bfloat16_rn(f);
    g_Bh[i] = hh;
    g_Bl[i] = __float2bfloat16_rn(f - __bfloat162float(hh));
}

// ---------------- pack index weights (fp32, exact) ----------------
__global__ __launch_bounds__(256) void packWi_kernel(
    const float* __restrict__ Wiq, const float* __restrict__ Wik,
    const float* __restrict__ Wiw)
{
    int i = blockIdx.x * 256 + threadIdx.x;
    if (i >= D * NIW) return;
    int k = i / NIW, c = i % NIW;
    float f;
    if      (c < 256) f = Wiq[k*256 + c];
    else if (c < 320) f = Wik[k*64  + c - 256];
    else if (c < 324) f = Wiw[k*4   + c - 320];
    else              f = 0.f;
    g_Wi[i] = f;
}

// ---------------- split-bf16 tensor-core GEMM (TERMS=3 exact / TERMS=1 plain bf16) ----------------
#define SA_STRIDE 40
#define SB_STRIDE 136
#define SA_SZ (128*SA_STRIDE)
#define SB_SZ (32*SB_STRIDE)
#define GEMM_SMEM ((2*2*SA_SZ + 2*2*SB_SZ)*2)

template<int TERMS>
__global__ __launch_bounds__(256) void mma_gemm(
    const __nv_bfloat16* __restrict__ Ah, const __nv_bfloat16* __restrict__ Al,
    const __nv_bfloat16* __restrict__ Bh, const __nv_bfloat16* __restrict__ Bl,
    float* __restrict__ C, int M, int N, int K)
{
    extern __shared__ __align__(16) char smem_raw[];
    __nv_bfloat16* sA = (__nv_bfloat16*)smem_raw;
    __nv_bfloat16* sB = (__nv_bfloat16*)(smem_raw + 2*2*SA_SZ*2);
    const int tid = threadIdx.x;
    const int m0 = blockIdx.y * 128, n0 = blockIdx.x * 128;

    const int wid = tid >> 5, lane = tid & 31;
    const int m0w = (wid & 1) * 64, n0w = (wid >> 1) * 32;
    const int a_row = (lane & 15);
    const int a_koff = (lane >> 4) * 8;
    const int l15 = lane & 15;
    const int b_krow = (l15 & 7) + (l15 >> 3) * 8;

    float acc[4][4][4];
    #pragma unroll
    for (int i = 0; i < 4; ++i)
        #pragma unroll
        for (int j = 0; j < 4; ++j)
            #pragma unroll
            for (int r = 0; r < 4; ++r) acc[i][j][r] = 0.f;

    auto load_stage = [&](int st, int k0) {
        __nv_bfloat16* aH = sA + (st*2+0)*SA_SZ;
        __nv_bfloat16* aL = sA + (st*2+1)*SA_SZ;
        __nv_bfloat16* bH = sB + (st*2+0)*SB_SZ;
        __nv_bfloat16* bL = sB + (st*2+1)*SB_SZ;
        #pragma unroll
        for (int i = 0; i < 2; ++i) {
            int c = tid + i * 256;
            int r = c >> 2, cc = (c & 3) * 8;
            cpa16(aH + r*SA_STRIDE + cc, Ah + (size_t)(m0 + r) * K + k0 + cc);
            if (TERMS == 3)
                cpa16(aL + r*SA_STRIDE + cc, Al + (size_t)(m0 + r) * K + k0 + cc);
            int rb = c >> 4, cb = (c & 15) * 8;
            cpa16(bH + rb*SB_STRIDE + cb, Bh + (size_t)(k0 + rb) * N + n0 + cb);
            if (TERMS == 3)
                cpa16(bL + rb*SB_STRIDE + cb, Bl + (size_t)(k0 + rb) * N + n0 + cb);
        }
        cp_commit();
    };

    load_stage(0, 0);
    const int KT = K / 32;
    for (int kt = 0; kt < KT; ++kt) {
        if (kt + 1 < KT) {
            load_stage((kt + 1) & 1, (kt + 1) * 32);
            asm volatile("cp.async.wait_group 1;\n");
        } else {
            asm volatile("cp.async.wait_group 0;\n");
        }
        __syncthreads();

        const int st = kt & 1;
        const __nv_bfloat16* aP[2] = { sA + (st*2+0)*SA_SZ, sA + (st*2+1)*SA_SZ };
        const __nv_bfloat16* bP[2] = { sB + (st*2+0)*SB_SZ, sB + (st*2+1)*SB_SZ };

        #pragma unroll
        for (int kk = 0; kk < 32; kk += 16) {
            uint32_t af[2][4][4];
            uint32_t bf[2][4][2];
            #pragma unroll
            for (int p = 0; p < (TERMS == 3 ? 2 : 1); ++p) {
                #pragma unroll
                for (int mt = 0; mt < 4; ++mt)
                    ldsm_x4(af[p][mt], aP[p] + (m0w + mt*16 + a_row)*SA_STRIDE + kk + a_koff);
                #pragma unroll
                for (int nt = 0; nt < 4; ++nt)
                    ldsm_x2t(bf[p][nt], bP[p] + (kk + b_krow)*SB_STRIDE + n0w + nt*8);
            }
            #pragma unroll
            for (int mt = 0; mt < 4; ++mt)
                #pragma unroll
                for (int nt = 0; nt < 4; ++nt) {
                    mma16816(acc[mt][nt], af[0][mt], bf[0][nt]);
                    if (TERMS == 3) {
                        mma16816(acc[mt][nt], af[0][mt], bf[1][nt]);
                        mma16816(acc[mt][nt], af[1][mt], bf[0][nt]);
                    }
                }
        }
        __syncthreads();
    }

    #pragma unroll
    for (int mt = 0; mt < 4; ++mt) {
        int row = m0 + m0w + mt*16 + (lane >> 2);
        #pragma unroll
        for (int nt = 0; nt < 4; ++nt) {
            int col = n0 + n0w + nt*8 + (lane & 3)*2;
            *(float2*)(C + (size_t)row * N + col)       = make_float2(acc[mt][nt][0], acc[mt][nt][1]);
            *(float2*)(C + (size_t)(row + 8) * N + col) = make_float2(acc[mt][nt][2], acc[mt][nt][3]);
        }
    }
}

// ---------------- fp32 SIMT SGEMM (exact path for top-k ranking inputs) ----------------
__global__ __launch_bounds__(256) void sgemm_kernel(
    const float* __restrict__ A, const float* __restrict__ B,
    float* __restrict__ C, int M, int N, int K)
{
    __shared__ float Ast[16][68];
    __shared__ float Bs [16][64];
    const int tid = threadIdx.x;
    const int m0 = blockIdx.y * 64, n0 = blockIdx.x * 64;
    const int tr = tid >> 4, tc = tid & 15;
    const int arow = tid >> 2, akq = tid & 3;
    const int brow = tid >> 4, bnq = tid & 15;

    float acc[4][4] = {};

    for (int k0 = 0; k0 < K; k0 += 16) {
        float4 av = *(const float4*)(A + (size_t)(m0 + arow) * K + k0 + akq * 4);
        Ast[akq*4+0][arow] = av.x;
        Ast[akq*4+1][arow] = av.y;
        Ast[akq*4+2][arow] = av.z;
        Ast[akq*4+3][arow] = av.w;

        float4 bv = *(const float4*)(B + (size_t)(k0 + brow) * N + n0 + bnq * 4);
        *(float4*)&Bs[brow][bnq * 4] = bv;
        __syncthreads();

        #pragma unroll
        for (int kk = 0; kk < 16; ++kk) {
            float4 a = *(float4*)&Ast[kk][tr * 4];
            float4 b = *(float4*)&Bs [kk][tc * 4];
            acc[0][0] += a.x * b.x; acc[0][1] += a.x * b.y; acc[0][2] += a.x * b.z; acc[0][3] += a.x * b.w;
            acc[1][0] += a.y * b.x; acc[1][1] += a.y * b.y; acc[1][2] += a.y * b.z; acc[1][3] += a.y * b.w;
            acc[2][0] += a.z * b.x; acc[2][1] += a.z * b.y; acc[2][2] += a.z * b.z; acc[2][3] += a.z * b.w;
            acc[3][0] += a.w * b.x; acc[3][1] += a.w * b.y; acc[3][2] += a.w * b.z; acc[3][3] += a.w * b.w;
        }
        __syncthreads();
    }

    #pragma unroll
    for (int i = 0; i < 4; ++i) {
        int r = m0 + tr * 4 + i;
        #pragma unroll
        for (int j = 0; j < 4; ++j)
            C[(size_t)r * N + n0 + tc * 4 + j] = acc[i][j];
    }
}

// ---------------- RoPE cos/sin table (fp32, matches reference) ----------------
__global__ __launch_bounds__(256) void rope_table_kernel()
{
    int i = blockIdx.x * 256 + threadIdx.x;
    if (i >= T * 32) return;
    int t = i >> 5, jm = i & 31;
    float invf = powf(10000.f, -(float)(2 * jm) / 64.f);
    float ph = (float)t * invf;
    float s, c;
    sincosf(ph, &s, &c);
    g_cs[i] = c;
    g_sn[i] = s;
}

// ---------------- RoPE(q,k) + v*sigmoid(vg+bvg) ----------------
__global__ __launch_bounds__(256) void ew_kernel(const float* __restrict__ bvg)
{
    int t = blockIdx.x, tid = threadIdx.x;
    float* row = g_big + (size_t)t * NB;
    __shared__ float sq[D], sk[D];
    sq[tid]       = row[OQ + tid];
    sq[tid + 256] = row[OQ + tid + 256];
    sk[tid]       = row[OK_ + tid];
    sk[tid + 256] = row[OK_ + tid + 256];
    __syncthreads();
    #pragma unroll
    for (int it = 0; it < 2; ++it) {
        int e = tid + it * 256;
        int j = e & 63, jm = j & 31;
        float cc = g_cs[t * 32 + jm], ss = g_sn[t * 32 + jm];
        float rq = (j < 32) ? -sq[e + 32] : sq[e - 32];
        float rk = (j < 32) ? -sk[e + 32] : sk[e - 32];
        row[OQ + e] = sq[e] * cc + rq * ss;
        g_k[(size_t)t * D + e] = sk[e] * cc + rk * ss;
        float vv = row[OV + e], vg = row[OVG + e];
        g_v[(size_t)t * D + e] = vv * (1.f / (1.f + expf(-(vg + bvg[e]))));
    }
}

// ---------------- index scores: 64x64 tile, 4x4/thread, TWO heads per pass ----------------
#define SCW_SMEM (3 * 64 * 68 * 4)

__global__ __launch_bounds__(256) void scores_kernel(const float* __restrict__ idx_bias,
                                                     const float* __restrict__ biw)
{
    const int q0 = blockIdx.y * 64, j0 = blockIdx.x * 64;
    if (j0 > q0 + 63) return;
    extern __shared__ float sdyn[];
    float* Kst = sdyn;               // [64][68]
    float* Q0  = sdyn + 64 * 68;     // even head of pair
    float* Q1  = sdyn + 2 * 64 * 68; // odd head of pair
    const int tid = threadIdx.x;
    const int tr = tid >> 4, tc = tid & 15;

    // K tile (once), transposed [dim][row]
    #pragma unroll
    for (int it = 0; it < 4; ++it) {
        int e = tid + it * 256;
        int r = e >> 4, quad = e & 15;
        float4 kv = *(const float4*)(g_ix + (size_t)(j0 + r) * NIW + OIK + quad * 4);
        Kst[(quad*4+0)*68 + r] = kv.x; Kst[(quad*4+1)*68 + r] = kv.y;
        Kst[(quad*4+2)*68 + r] = kv.z; Kst[(quad*4+3)*68 + r] = kv.w;
    }

    float fin[4][4] = {};
    for (int hp = 0; hp < 2; ++hp) {
        if (hp) __syncthreads();
        const int h0 = 2 * hp, h1 = 2 * hp + 1;
        #pragma unroll
        for (int it = 0; it < 4; ++it) {
            int e = tid + it * 256;
            int r = e >> 4, quad = e & 15;
            const float* base = g_ix + (size_t)(q0 + r) * NIW + OIQ;
            float4 qa = *(const float4*)(base + h0 * DI + quad * 4);
            float4 qb = *(const float4*)(base + h1 * DI + quad * 4);
            Q0[(quad*4+0)*68 + r] = qa.x; Q0[(quad*4+1)*68 + r] = qa.y;
            Q0[(quad*4+2)*68 + r] = qa.z; Q0[(quad*4+3)*68 + r] = qa.w;
            Q1[(quad*4+0)*68 + r] = qb.x; Q1[(quad*4+1)*68 + r] = qb.y;
            Q1[(quad*4+2)*68 + r] = qb.z; Q1[(quad*4+3)*68 + r] = qb.w;
        }
        __syncthreads();

        float dA[4][4] = {}, dB[4][4] = {};
        #pragma unroll 4
        for (int kk = 0; kk < 64; ++kk) {
            float4 a0 = *(float4*)(Q0 + kk*68 + tr*4);
            float4 a1 = *(float4*)(Q1 + kk*68 + tr*4);
            float4 b  = *(float4*)(Kst + kk*68 + tc*4);
            dA[0][0] += a0.x*b.x; dA[0][1] += a0.x*b.y; dA[0][2] += a0.x*b.z; dA[0][3] += a0.x*b.w;
            dA[1][0] += a0.y*b.x; dA[1][1] += a0.y*b.y; dA[1][2] += a0.y*b.z; dA[1][3] += a0.y*b.w;
            dA[2][0] += a0.z*b.x; dA[2][1] += a0.z*b.y; dA[2][2] += a0.z*b.z; dA[2][3] += a0.z*b.w;
            dA[3][0] += a0.w*b.x; dA[3][1] += a0.w*b.y; dA[3][2] += a0.w*b.z; dA[3][3] += a0.w*b.w;
            dB[0][0] += a1.x*b.x; dB[0][1] += a1.x*b.y; dB[0][2] += a1.x*b.z; dB[0][3] += a1.x*b.w;
            dB[1][0] += a1.y*b.x; dB[1][1] += a1.y*b.y; dB[1][2] += a1.y*b.z; dB[1][3] += a1.y*b.w;
            dB[2][0] += a1.z*b.x; dB[2][1] += a1.z*b.y; dB[2][2] += a1.z*b.z; dB[2][3] += a1.z*b.w;
            dB[3][0] += a1.w*b.x; dB[3][1] += a1.w*b.y; dB[3][2] += a1.w*b.z; dB[3][3] += a1.w*b.w;
        }

        // fin updated in head order (h0 then h1) -> bit-identical to per-head loop
        float bh0 = idx_bias[h0], bw0 = biw[h0];
        float bh1 = idx_bias[h1], bw1 = biw[h1];
        #pragma unroll
        for (int i = 0; i < 4; ++i) {
            const float* wrow = g_ix + (size_t)(q0 + tr * 4 + i) * NIW + OIW;
            float ws0 = 1.f / (1.f + expf(-(wrow[h0] + bw0)));
            float ws1 = 1.f / (1.f + expf(-(wrow[h1] + bw1)));
            #pragma unroll
            for (int j = 0; j < 4; ++j) {
                fin[i][j] += ws0 * (1.f / (1.f + expf(-(dA[i][j] * 0.125f + bh0))));
                fin[i][j] += ws1 * (1.f / (1.f + expf(-(dB[i][j] * 0.125f + bh1))));
            }
        }
    }

    #pragma unroll
    for (int i = 0; i < 4; ++i) {
        int qq = q0 + tr * 4 + i;
        #pragma unroll
        for (int j = 0; j < 4; ++j) {
            int jj = j0 + tc * 4 + j;
            if (jj <= qq) g_sc[(size_t)qq * T + jj] = fin[i][j];
        }
    }
}

// ---------------- exact top-128: radix select (R7 measured version) ----------------
__global__ __launch_bounds__(256) void topk_kernel()
{
    const int q = blockIdx.x;
    const int n = q + 1;
    const int tid = threadIdx.x;
    const int lane = tid & 31;
    const int wid = tid >> 5;

    if (n <= KSEL) {
        for (int j = tid; j < n; j += 256) g_idx[q * KSEL + j] = j;
        return;
    }

    __shared__ unsigned sbits[T];
    const float* row = g_sc + (size_t)q * T;
    for (int j = tid; j < n; j += 256)
        sbits[j] = __float_as_uint(row[j]);

    __shared__ unsigned hist[256];
    __shared__ unsigned wtot[8], wsuf[8];
    __shared__ unsigned s_pref;
    __shared__ int s_need;
    unsigned pref = 0;
    int need = KSEL;
    const int nIter = (n + 255) >> 8;

    for (int pass = 3; pass >= 0; --pass) {
        hist[tid] = 0;
        __syncthreads();
        const int sh = pass * 8;
        for (int it = 0; it < nIter; ++it) {
            int j = it * 256 + tid;
            unsigned b = (j < n) ? sbits[j] : 0u;
            bool ok = (j < n) && (pass == 3 || (b >> (sh + 8)) == pref);
            unsigned d = (b >> sh) & 255u;
            unsigned active = __ballot_sync(0xffffffffu, ok);
            if (ok) {
                unsigned peers = __match_any_sync(active, d);
                if (lane == __ffs(peers) - 1)
                    atomicAdd(&hist[d], (unsigned)__popc(peers));
            }
        }
        __syncthreads();

        unsigned hv = hist[tid];
        unsigned v = hv;
        #pragma unroll
        for (int off = 1; off < 32; off <<= 1) {
            unsigned t2 = __shfl_down_sync(0xffffffffu, v, off);
            if (lane < 32 - off) v += t2;
        }
        if (lane == 0) wtot[wid] = v;
        __syncthreads();
        if (tid < 8) {
            unsigned s = 0;
            for (int w2 = tid + 1; w2 < 8; ++w2) s += wtot[w2];
            wsuf[tid] = s;
        }
        __syncthreads();
        unsigned incl  = v + wsuf[wid];
        unsigned above = incl - hv;
        if (incl >= (unsigned)need && above < (unsigned)need) {
            s_pref = (pref << 8) | (unsigned)tid;
            s_need = need - (int)above;
        }
        __syncthreads();
        pref = s_pref;
        need = s_need;
    }

    const unsigned thr = pref;
    __shared__ int wcnt;
    __shared__ int eqi[256];
    __shared__ int ecnt;
    if (tid == 0) { wcnt = 0; ecnt = 0; }
    __syncthreads();
    for (int j = tid; j < n; j += 256) {
        unsigned b = sbits[j];
        if (b > thr) {
            int p = atomicAdd(&wcnt, 1);
            g_idx[q * KSEL + p] = j;
        } else if (b == thr) {
            int p = atomicAdd(&ecnt, 1);
            if (p < 256) eqi[p] = j;
        }
    }
    __syncthreads();
    if (tid == 0) {
        int E = min(ecnt, 256);
        for (int a = 1; a < E; ++a) {
            int v2 = eqi[a]; int b = a - 1;
            while (b >= 0 && eqi[b] > v2) { eqi[b + 1] = eqi[b]; --b; }
            eqi[b + 1] = v2;
        }
        int base = wcnt;
        for (int e2 = 0; e2 < need && e2 < E; ++e2)
            g_idx[q * KSEL + base + e2] = eqi[e2];
    }
}

// ---------------- sparse attention (warp-per-key QK — R7 measured version) ----------------
__global__ __launch_bounds__(256) void attn_kernel(const float* __restrict__ bog)
{
    const int q = blockIdx.x;
    const int c = min(q + 1, KSEL);
    __shared__ int sidx[KSEL];
    __shared__ __align__(16) float qv[D];
    __shared__ float sp[NH][KSEL + 4];
    const int tid = threadIdx.x;
    const int w = tid >> 5, lane = tid & 31;
    const float* brow = g_big + (size_t)q * NB;

    if (tid < c) sidx[tid] = g_idx[q * KSEL + tid];
    qv[tid]       = brow[OQ + tid];
    qv[tid + 256] = brow[OQ + tid + 256];
    __syncthreads();

    {
        float4 q0 = *(const float4*)(qv + lane * 4);
        float4 q1 = *(const float4*)(qv + 128 + lane * 4);
        float4 q2 = *(const float4*)(qv + 256 + lane * 4);
        float4 q3 = *(const float4*)(qv + 384 + lane * 4);
        #pragma unroll 4
        for (int t = 0; t < 16; ++t) {
            int jj = w * 16 + t;
            if (jj < c) {
                const float4* kr = (const float4*)(g_k + (size_t)sidx[jj] * D);
                float4 k0 = kr[lane], k1 = kr[lane + 32], k2 = kr[lane + 64], k3 = kr[lane + 96];
                float p0 = q0.x*k0.x + q0.y*k0.y + q0.z*k0.z + q0.w*k0.w;
                float p1 = q1.x*k1.x + q1.y*k1.y + q1.z*k1.z + q1.w*k1.w;
                float p2 = q2.x*k2.x + q2.y*k2.y + q2.z*k2.z + q2.w*k2.w;
                float p3 = q3.x*k3.x + q3.y*k3.y + q3.z*k3.z + q3.w*k3.w;
                #pragma unroll
                for (int o = 1; o < 16; o <<= 1) {
                    p0 += __shfl_xor_sync(0xffffffffu, p0, o);
                    p1 += __shfl_xor_sync(0xffffffffu, p1, o);
                    p2 += __shfl_xor_sync(0xffffffffu, p2, o);
                    p3 += __shfl_xor_sync(0xffffffffu, p3, o);
                }
                if ((lane & 15) == 0) {
                    int hi = lane >> 4;
                    sp[0 + hi][jj] = p0 * 0.125f;
                    sp[2 + hi][jj] = p1 * 0.125f;
                    sp[4 + hi][jj] = p2 * 0.125f;
                    sp[6 + hi][jj] = p3 * 0.125f;
                }
            }
        }
    }
    __syncthreads();

    {
        float m = -1e30f;
        for (int jj = lane; jj < c; jj += 32) m = fmaxf(m, sp[w][jj]);
        #pragma unroll
        for (int o = 16; o; o >>= 1) m = fmaxf(m, __shfl_xor_sync(0xffffffffu, m, o));
        float s = 0.f;
        for (int jj = lane; jj < c; jj += 32) { float e = expf(sp[w][jj] - m); sp[w][jj] = e; s += e; }
        #pragma unroll
        for (int o = 16; o; o >>= 1) s += __shfl_xor_sync(0xffffffffu, s, o);
        float inv = 1.f / s;
        for (int jj = lane; jj < c; jj += 32) sp[w][jj] *= inv;
    }
    __syncthreads();

    {
        const int e2 = tid;
        const int h = e2 >> 5;
        const float* spr = sp[h];
        const float2* vb = (const float2*)g_v;
        float2 acc = make_float2(0.f, 0.f);
        int jj = 0;
        for (; jj + 4 <= c; jj += 4) {
            float w0 = spr[jj+0], w1 = spr[jj+1], w2 = spr[jj+2], w3 = spr[jj+3];
            float2 v0 = vb[(size_t)sidx[jj+0] * 256 + e2];
            float2 v1 = vb[(size_t)sidx[jj+1] * 256 + e2];
            float2 v2 = vb[(size_t)sidx[jj+2] * 256 + e2];
            float2 v3 = vb[(size_t)sidx[jj+3] * 256 + e2];
            acc.x += w0 * v0.x + w1 * v1.x + w2 * v2.x + w3 * v3.x;
            acc.y += w0 * v0.y + w1 * v1.y + w2 * v2.y + w3 * v3.y;
        }
        for (; jj < c; ++jj) {
            float ww = spr[jj];
            float2 v = vb[(size_t)sidx[jj] * 256 + e2];
            acc.x += ww * v.x;
            acc.y += ww * v.y;
        }
        int e = e2 * 2;
        float g0 = 1.f / (1.f + expf(-(brow[OOG + e]     + bog[e])));
        float g1 = 1.f / (1.f + expf(-(brow[OOG + e + 1] + bog[e + 1])));
        *(float2*)(g_ao + (size_t)q * D + e) = make_float2(acc.x * g0, acc.y * g1);
    }
}

// ---------------- launch ----------------
extern "C" void kernel_launch(void* const* d_in, const int* in_sizes, int n_in,
                              void* d_out, int out_size)
{
    const float* x        = (const float*)d_in[0];
    const float* Wq       = (const float*)d_in[1];
    const float* Wk       = (const float*)d_in[2];
    const float* Wv       = (const float*)d_in[3];
    const float* Wo       = (const float*)d_in[4];
    const float* Wiq      = (const float*)d_in[5];
    const float* Wik      = (const float*)d_in[6];
    const float* Wiw      = (const float*)d_in[7];
    const float* biw      = (const float*)d_in[8];
    const float* idx_bias = (const float*)d_in[9];
    const float* Wvg      = (const float*)d_in[10];
    const float* bvg      = (const float*)d_in[11];
    const float* Wog      = (const float*)d_in[12];
    const float* bog      = (const float*)d_in[13];
    float* out = (float*)d_out;

    float *pbig, *pao, *pix, *pWi;
    __nv_bfloat16 *pAh, *pAl, *pBh, *pBl, *pAoH, *pAoL, *pWoH, *pWoL;
    cudaGetSymbolAddress((void**)&pbig, g_big);
    cudaGetSymbolAddress((void**)&pao,  g_ao);
    cudaGetSymbolAddress((void**)&pix,  g_ix);
    cudaGetSymbolAddress((void**)&pWi,  g_Wi);
    cudaGetSymbolAddress((void**)&pAh,  g_Ah);
    cudaGetSymbolAddress((void**)&pAl,  g_Al);
    cudaGetSymbolAddress((void**)&pBh,  g_Bh);
    cudaGetSymbolAddress((void**)&pBl,  g_Bl);
    cudaGetSymbolAddress((void**)&pAoH, g_AoH);
    cudaGetSymbolAddress((void**)&pAoL, g_AoL);
    cudaGetSymbolAddress((void**)&pWoH, g_WoH);
    cudaGetSymbolAddress((void**)&pWoL, g_WoL);

    cudaFuncSetAttribute(mma_gemm<3>, cudaFuncAttributeMaxDynamicSharedMemorySize, GEMM_SMEM);
    cudaFuncSetAttribute(mma_gemm<1>, cudaFuncAttributeMaxDynamicSharedMemorySize, GEMM_SMEM);
    cudaFuncSetAttribute(scores_kernel, cudaFuncAttributeMaxDynamicSharedMemorySize, SCW_SMEM);

    static cudaStream_t s1 = nullptr;
    static cudaEvent_t evF = nullptr, evJ = nullptr;
    if (s1 == nullptr) {
        cudaStreamCreateWithFlags(&s1, cudaStreamNonBlocking);
        cudaEventCreateWithFlags(&evF, cudaEventDisableTiming);
        cudaEventCreateWithFlags(&evJ, cudaEventDisableTiming);
    }

    dim3 th(256);

    // ---- fork: index/top-k chain on s1 ----
    cudaEventRecord(evF, 0);
    cudaStreamWaitEvent(s1, evF, 0);

    packWi_kernel<<<(D*NIW + 255)/256, th, 0, s1>>>(Wiq, Wik, Wiw);
    sgemm_kernel<<<dim3(NIW/64, T/64), th, 0, s1>>>(x, pWi, pix, T, NIW, D);
    scores_kernel<<<dim3(32, 32), th, SCW_SMEM, s1>>>(idx_bias, biw);
    topk_kernel<<<T, th, 0, s1>>>();
    cudaEventRecord(evJ, s1);

    // ---- projection chain on the capture stream ----
    split_kernel<<<(T*D + 255)/256, th>>>(x, pAh, pAl, T*D);
    packB_kernel<<<(D*NB + 255)/256, th>>>(Wq, Wk, Wv, Wvg, Wog);
    split_kernel<<<(D*D + 255)/256, th>>>(Wo, pWoH, pWoL, D*D);
    rope_table_kernel<<<(T*32 + 255)/256, th>>>();
    // exact (3-term) part: Wq|Wk|Wv
    mma_gemm<3><<<dim3(NQKV/128, T/128), th, GEMM_SMEM>>>(pAh, pAl, pBh, pBl, pbig, T, NB, D);
    // gate part: Wvg|Wog plain bf16 (sigmoid-smoothed; validated 5.1e-4)
    mma_gemm<1><<<dim3((NB-NQKV)/128, T/128), th, GEMM_SMEM>>>(pAh, pAl, pBh + NQKV, pBl + NQKV,
                                                               pbig + NQKV, T, NB, D);
    ew_kernel<<<T, th>>>(bvg);

    // ---- join, then attention + output projection ----
    cudaStreamWaitEvent(0, evJ, 0);
    attn_kernel<<<T, th>>>(bog);
    split_kernel<<<(T*D + 255)/256, th>>>(pao, pAoH, pAoL, T*D);
    mma_gemm<3><<<dim3(D/128, T/128), th, GEMM_SMEM>>>(pAoH, pAoL, pWoH, pWoL, out, T, D, D);
}